// round 14
// baseline (speedup 1.0000x reference)
#include <cuda_runtime.h>
#include <cuda_fp16.h>
#include <stdint.h>

// ==========================================================================
// SyllableProcessor on GB300 (sm_103 base target — tcgen05 unavailable).
//   out = char + GELU(LN( [char, (comb@W1+b1)] @ W2 + b2 )),  comb=[char,gather]
// R14: R13 champion + dedicated SM_ALN region for the GEMM1->GEMM2 aligned
//      tile. The rewrite no longer overwrites SM_TOK, so the c==16 full-CTA
//      drain barrier is DELETED (rewrite is barrier-free; the single c==24
//      barrier provides visibility before the first aligned read).
//      Mainloop barriers: 2 -> 1. Smem 103KB/CTA, still 2 CTAs/SM.
// Model: mainloop is L1/tensor equilibrium (48KB/step re-tiling invariant;
//      tensor 59.5% == exact rt=8 HMMA floor) — only phase/barrier time left.
// ==========================================================================

#define HD       256
#define TILE_M   64
#define LC_SHIFT 14          // Lc = 16384
#define SEQ_S    2048
#define THREADS  256

// dynamic smem layout
#define SM_CHAR   1024                    // 4 chunks x 8KB (char fp16, SW128)
#define SM_TOK    (SM_CHAR + 4 * 8192)    // 4 chunks x 8KB (tok, GEMM1 only)
#define SM_ALN    (SM_TOK  + 4 * 8192)    // 4 chunks x 8KB (aligned, GEMM2 A)
#define SM_PARAM  (SM_ALN  + 4 * 8192)    // b1,b2,gamma,beta
#define SM_PART   (SM_PARAM + 4 * HD * 4) // [64][4][2] partial sums
#define SMEM_TOTAL (SM_PART + 64 * 4 * 2 * 4)

#define SWZ(o)   ((o) ^ (((o) >> 3) & 0x70))   // SW128 (A tiles)

// fragment-major fp16 weight image: [c 0..31][kk 0..1][wn 0..3][g 0..3][lane]
// uint4 per lane = the exact 4 b32 MMA B-fragment registers for that step.
__device__ __align__(16) unsigned char g_wimg[32 * 2 * 4 * 4 * 512];

// ---------------- helpers ----------------
static __device__ __forceinline__ uint32_t smem_u32(const void* p) {
    uint32_t a;
    asm("{ .reg .u64 t; cvta.to.shared.u64 t, %1; cvt.u32.u64 %0, t; }"
        : "=r"(a) : "l"(p));
    return a;
}
static __device__ __forceinline__ uint32_t f2h2(float x, float y) {
    __half2 h = __floats2half2_rn(x, y);
    return *reinterpret_cast<uint32_t*>(&h);
}
static __device__ __forceinline__ void ldsm4(uint32_t* r, uint32_t addr) {
    asm volatile("ldmatrix.sync.aligned.m8n8.x4.shared.b16 {%0,%1,%2,%3}, [%4];"
                 : "=r"(r[0]), "=r"(r[1]), "=r"(r[2]), "=r"(r[3]) : "r"(addr));
}
static __device__ __forceinline__ void mma16816(float* d, const uint32_t* a,
                                                const uint32_t* b) {
    asm volatile(
        "mma.sync.aligned.m16n8k16.row.col.f32.f16.f16.f32 "
        "{%0,%1,%2,%3}, {%4,%5,%6,%7}, {%8,%9}, {%0,%1,%2,%3};"
        : "+f"(d[0]), "+f"(d[1]), "+f"(d[2]), "+f"(d[3])
        : "r"(a[0]), "r"(a[1]), "r"(a[2]), "r"(a[3]), "r"(b[0]), "r"(b[1]));
}
// tanh-formulation GELU: 1 MUFU + ~6 flops
static __device__ __forceinline__ float gelu_t(float x) {
    float u = x * (0.7978845608028654f + 0.03567740814183479f * x * x);
    float t;
    asm("tanh.approx.f32 %0, %1;" : "=f"(t) : "f"(u));
    return 0.5f * x * (1.0f + t);
}

// ---------------- weight prep: fp32 W[512,256] -> fragment-major fp16 image --
__global__ void prep_w(const float* __restrict__ W1, const float* __restrict__ W2) {
    int t = blockIdx.x * blockDim.x + threadIdx.x;   // 0..32767 -> one uint4
    int lane = t & 31;
    int g    = (t >> 5) & 3;
    int wn   = (t >> 7) & 3;
    int kk   = (t >> 9) & 1;
    int c    = t >> 10;                              // 0..31
    const float* W = (c >> 4) ? W2 : W1;
    const int kbase = (c & 15) * 32 + kk * 16 + (lane & 3) * 2;
    uint4 pk;
    uint32_t v[4];
#pragma unroll
    for (int e = 0; e < 4; e++) {
        const int jh = e >> 1, br = e & 1;
        const int n = wn * 64 + g * 16 + jh * 8 + (lane >> 2);
        const int k = kbase + br * 8;
        v[e] = f2h2(W[k * 256 + n], W[(k + 1) * 256 + n]);
    }
    pk.x = v[0]; pk.y = v[1]; pk.z = v[2]; pk.w = v[3];
    reinterpret_cast<uint4*>(g_wimg)[t] = pk;
}

// ---------------- main kernel ----------------
__global__ __launch_bounds__(THREADS, 2)
void syl_main(const float* __restrict__ cemb, const int* __restrict__ alig,
              const float* __restrict__ dec,
              const float* __restrict__ b1, const float* __restrict__ b2,
              const float* __restrict__ gamma, const float* __restrict__ beta,
              float* __restrict__ outp)
{
    extern __shared__ __align__(1024) unsigned char smem[];
    const uint32_t sb = smem_u32(smem);
    const int tid = threadIdx.x;
    const int wid = tid >> 5, lid = tid & 31;
    const int wm = wid >> 2, wn = wid & 3;        // 2 x 4 warp grid (32m x 64n)
    const size_t r0 = (size_t)blockIdx.x * TILE_M;

    // params -> smem
    float* sp = reinterpret_cast<float*>(smem + SM_PARAM);
    for (int i = tid; i < HD; i += THREADS) {
        sp[i]          = __ldg(b1 + i);
        sp[HD + i]     = __ldg(b2 + i);
        sp[2 * HD + i] = __ldg(gamma + i);
        sp[3 * HD + i] = __ldg(beta + i);
    }

    // B-fragment base for this thread; preload step (c=0, kk=0)
    const unsigned char* bbase = g_wimg + (size_t)(wn * 2048 + lid * 16);
    uint32_t bb[2][16];
#pragma unroll
    for (int g = 0; g < 4; g++)
        *reinterpret_cast<uint4*>(&bb[0][g * 4]) =
            __ldg(reinterpret_cast<const uint4*>(bbase + g * 512));

    // ---- phase L: char + gathered tok tiles, fp32 -> fp16, SW128 ----
    {
        const int c0   = lid * 8;                 // 8 consecutive cols per lane
        const int chnk = c0 >> 6;
        const int cc   = c0 & 63;
        int idxv[8];
#pragma unroll
        for (int i = 0; i < 8; i++)
            idxv[i] = __ldg(alig + r0 + i * 8 + wid);
#pragma unroll
        for (int i = 0; i < 8; i++) {
            const int m = i * 8 + wid;            // warp-per-row: idx uniform per warp
            const size_t rg = r0 + m;
            const float4* cp = reinterpret_cast<const float4*>(cemb + rg * HD + c0);
            float4 a0 = __ldg(cp), a1 = __ldg(cp + 1);
            uint32_t swo = SWZ((uint32_t)(m * 128 + cc * 2));
            uint4 pk;
            pk.x = f2h2(a0.x, a0.y); pk.y = f2h2(a0.z, a0.w);
            pk.z = f2h2(a1.x, a1.y); pk.w = f2h2(a1.z, a1.w);
            *reinterpret_cast<uint4*>(smem + SM_CHAR + chnk * 8192 + swo) = pk;

            const int idraw = idxv[i];
            int idc = idraw < 0 ? 0 : (idraw > (SEQ_S - 1) ? (SEQ_S - 1) : idraw);
            float4 t0 = make_float4(0.f, 0.f, 0.f, 0.f), t1 = t0;
            if (idraw >= 0) {
                const float4* dp = reinterpret_cast<const float4*>(
                    dec + ((rg >> LC_SHIFT) * SEQ_S + (size_t)idc) * HD + c0);
                t0 = __ldg(dp); t1 = __ldg(dp + 1);
            }
            uint4 pt;
            pt.x = f2h2(t0.x, t0.y); pt.y = f2h2(t0.z, t0.w);
            pt.z = f2h2(t1.x, t1.y); pt.w = f2h2(t1.z, t1.w);
            *reinterpret_cast<uint4*>(smem + SM_TOK + chnk * 8192 + swo) = pt;
        }
    }
    __syncthreads();

    // ---- 32 K-chunks (K=32 each): c 0..15 GEMM1, c 16..31 GEMM2 ----
    // Barrier-free B from global; A from smem. ONE mainloop barrier (c==24).
    float acc[2][8][4];
#pragma unroll
    for (int i = 0; i < 2; i++)
#pragma unroll
        for (int j = 0; j < 8; j++)
#pragma unroll
            for (int e = 0; e < 4; e++) acc[i][j][e] = 0.f;

    const uint32_t lxor = (uint32_t)((lid & 7) << 4);       // SW128 XOR (A)
    const uint32_t arow = (uint32_t)(wm * 32 + (lid & 15)); // + i*16
    const uint32_t akh  = (uint32_t)((lid >> 4) * 16);      // k-half byte offset

#pragma unroll 1
    for (int c = 0; c < 32; c++) {
        if (c == 16) {
            // GEMM1 done for THIS warp: aligned = acc + b1 -> fp16 into SM_ALN.
            // No barrier needed: SM_ALN conflicts with nothing (tok untouched);
            // readers are fenced by the single c==24 visibility barrier.
#pragma unroll
            for (int i = 0; i < 2; i++) {
                const uint32_t rr = (uint32_t)(wm * 32 + i * 16 + (lid >> 2));
                const uint32_t rx = ((rr & 7) << 4);
#pragma unroll
                for (int j = 0; j < 8; j++) {
                    const int cl = j * 8 + (lid & 3) * 2;       // local col in warp block
                    const int ng = wn * 64 + cl;                // global n (k of GEMM2)
                    uint32_t v01 = f2h2(acc[i][j][0] + sp[ng], acc[i][j][1] + sp[ng + 1]);
                    uint32_t v23 = f2h2(acc[i][j][2] + sp[ng], acc[i][j][3] + sp[ng + 1]);
                    uint32_t co = ((uint32_t)(cl * 2)) ^ rx;
                    *reinterpret_cast<uint32_t*>(
                        smem + SM_ALN + wn * 8192 + rr * 128 + co) = v01;
                    *reinterpret_cast<uint32_t*>(
                        smem + SM_ALN + wn * 8192 + (rr + 8) * 128 + co) = v23;
                    acc[i][j][0] = acc[i][j][1] = acc[i][j][2] = acc[i][j][3] = 0.f;
                }
            }
        }
        if (c == 24) __syncthreads();             // aligned rewrite visible to all

        const int cc   = c & 15;
        const int half = cc & 1;                  // which 64B half of A's 128B row
        const uint32_t abase = sb + ((c < 16)
            ? ((cc < 8) ? (uint32_t)(SM_CHAR + (cc >> 1) * 8192)
                        : (uint32_t)(SM_TOK + ((cc - 8) >> 1) * 8192))
            : ((cc < 8) ? (uint32_t)(SM_CHAR + (cc >> 1) * 8192)
                        : (uint32_t)(SM_ALN + ((cc - 8) >> 1) * 8192)));
        const unsigned char* bstep = bbase + (size_t)c * 16384;

#pragma unroll
        for (int kk = 0; kk < 2; kk++) {
            // prefetch next K16-step's B fragments into the other buffer
            if (c < 31 || kk == 0) {
                const unsigned char* bn = bstep + (kk == 0 ? 8192 : 16384);
#pragma unroll
                for (int g = 0; g < 4; g++)
                    *reinterpret_cast<uint4*>(&bb[kk ^ 1][g * 4]) =
                        __ldg(reinterpret_cast<const uint4*>(bn + g * 512));
            }
            uint32_t a[2][4];
#pragma unroll
            for (int i = 0; i < 2; i++) {
                uint32_t addr = abase + (arow + i * 16) * 128
                              + (((uint32_t)(half * 64 + kk * 32) + akh) ^ lxor);
                ldsm4(a[i], addr);
            }
#pragma unroll
            for (int i = 0; i < 2; i++)
#pragma unroll
                for (int j = 0; j < 8; j++)
                    mma16816(acc[i][j], a[i], &bb[kk][j * 2]);
        }
    }

    // ---- register-resident epilogue: +b2, LN, GELU, +char (char from smem) ----
    {
        const float* b2s = sp + HD;
        float* P = reinterpret_cast<float*>(smem + SM_PART);   // [64][4][2]
#pragma unroll
        for (int i = 0; i < 2; i++) {
            float sA = 0.f, qA = 0.f, sB = 0.f, qB = 0.f;
#pragma unroll
            for (int j = 0; j < 8; j++) {
                const int n = wn * 64 + j * 8 + (lid & 3) * 2;
                float f0 = acc[i][j][0] + b2s[n];
                float f1 = acc[i][j][1] + b2s[n + 1];
                float f2 = acc[i][j][2] + b2s[n];
                float f3 = acc[i][j][3] + b2s[n + 1];
                acc[i][j][0] = f0; acc[i][j][1] = f1;
                acc[i][j][2] = f2; acc[i][j][3] = f3;
                sA += f0 + f1; qA += f0 * f0 + f1 * f1;
                sB += f2 + f3; qB += f2 * f2 + f3 * f3;
            }
            sA += __shfl_xor_sync(0xffffffffu, sA, 1);
            qA += __shfl_xor_sync(0xffffffffu, qA, 1);
            sB += __shfl_xor_sync(0xffffffffu, sB, 1);
            qB += __shfl_xor_sync(0xffffffffu, qB, 1);
            sA += __shfl_xor_sync(0xffffffffu, sA, 2);
            qA += __shfl_xor_sync(0xffffffffu, qA, 2);
            sB += __shfl_xor_sync(0xffffffffu, sB, 2);
            qB += __shfl_xor_sync(0xffffffffu, qB, 2);
            if ((lid & 3) == 0) {
                const int rA = wm * 32 + i * 16 + (lid >> 2);
                const int rB = rA + 8;
                P[rA * 8 + wn * 2 + 0] = sA; P[rA * 8 + wn * 2 + 1] = qA;
                P[rB * 8 + wn * 2 + 0] = sB; P[rB * 8 + wn * 2 + 1] = qB;
            }
        }
        __syncthreads();

        const float* gms = sp + 2 * HD;
        const float* bts = sp + 3 * HD;
#pragma unroll
        for (int i = 0; i < 2; i++) {
            const int rA = wm * 32 + i * 16 + (lid >> 2);
            const int rB = rA + 8;
            float2 pa0 = *reinterpret_cast<const float2*>(P + rA * 8 + 0);
            float2 pa1 = *reinterpret_cast<const float2*>(P + rA * 8 + 2);
            float2 pa2 = *reinterpret_cast<const float2*>(P + rA * 8 + 4);
            float2 pa3 = *reinterpret_cast<const float2*>(P + rA * 8 + 6);
            float2 pb0 = *reinterpret_cast<const float2*>(P + rB * 8 + 0);
            float2 pb1 = *reinterpret_cast<const float2*>(P + rB * 8 + 2);
            float2 pb2 = *reinterpret_cast<const float2*>(P + rB * 8 + 4);
            float2 pb3 = *reinterpret_cast<const float2*>(P + rB * 8 + 6);
            float sA = pa0.x + pa1.x + pa2.x + pa3.x;
            float qA = pa0.y + pa1.y + pa2.y + pa3.y;
            float sB = pb0.x + pb1.x + pb2.x + pb3.x;
            float qB = pb0.y + pb1.y + pb2.y + pb3.y;
            const float muA = sA * (1.0f / HD);
            const float rsA = rsqrtf(qA * (1.0f / HD) - muA * muA + 1e-5f);
            const float muB = sB * (1.0f / HD);
            const float rsB = rsqrtf(qB * (1.0f / HD) - muB * muB + 1e-5f);
            const size_t gA = (r0 + rA) * HD, gB = (r0 + rB) * HD;
            const uint32_t rxA = ((uint32_t)(rA & 7)) << 4;   // rB&7 == rA&7
#pragma unroll
            for (int j = 0; j < 8; j++) {
                const int cl = j * 8 + (lid & 3) * 2;
                const int n = wn * 64 + cl;
                const float g0 = gms[n], g1 = gms[n + 1];
                const float t0 = bts[n], t1 = bts[n + 1];
                const uint32_t co = ((uint32_t)(cl * 2)) ^ rxA;
                __half2 hcA = *reinterpret_cast<const __half2*>(
                    smem + SM_CHAR + wn * 8192 + rA * 128 + co);
                __half2 hcB = *reinterpret_cast<const __half2*>(
                    smem + SM_CHAR + wn * 8192 + rB * 128 + co);
                float2 chA = __half22float2(hcA);
                float2 chB = __half22float2(hcB);
                float hA0 = (acc[i][j][0] - muA) * rsA * g0 + t0;
                float hA1 = (acc[i][j][1] - muA) * rsA * g1 + t1;
                float hB0 = (acc[i][j][2] - muB) * rsB * g0 + t0;
                float hB1 = (acc[i][j][3] - muB) * rsB * g1 + t1;
                float2 oA, oB;
                oA.x = chA.x + gelu_t(hA0);
                oA.y = chA.y + gelu_t(hA1);
                oB.x = chB.x + gelu_t(hB0);
                oB.y = chB.y + gelu_t(hB1);
                *reinterpret_cast<float2*>(outp + gA + n) = oA;
                *reinterpret_cast<float2*>(outp + gB + n) = oB;
            }
        }
    }
}

// ---------------- launch ----------------
extern "C" void kernel_launch(void* const* d_in, const int* in_sizes, int n_in,
                              void* d_out, int out_size) {
    const float* cemb  = (const float*)d_in[0];
    const int*   alig  = (const int*)d_in[1];
    const float* dec   = (const float*)d_in[2];
    const float* W1    = (const float*)d_in[3];
    const float* b1    = (const float*)d_in[4];
    const float* W2    = (const float*)d_in[5];
    const float* b2    = (const float*)d_in[6];
    const float* gamma = (const float*)d_in[7];
    const float* beta  = (const float*)d_in[8];
    float* outp = (float*)d_out;

    prep_w<<<128, 256>>>(W1, W2);

    cudaFuncSetAttribute(syl_main, cudaFuncAttributeMaxDynamicSharedMemorySize, SMEM_TOTAL);
    const int rows  = in_sizes[0] / HD;     // B * Lc = 131072 (from char elem count)
    const int tiles = rows / TILE_M;        // 2048
    syl_main<<<tiles, THREADS, SMEM_TOTAL>>>(cemb, alig, dec, b1, b2, gamma, beta, outp);
}

// round 15
// speedup vs baseline: 1.1108x; 1.1108x over previous
#include <cuda_runtime.h>
#include <cuda_fp16.h>
#include <stdint.h>

// ==========================================================================
// SyllableProcessor on GB300 (sm_103 base target — tcgen05 unavailable).
//   out = char + GELU(LN( [char, (comb@W1+b1)] @ W2 + b2 )),  comb=[char,gather]
// R15: ALGEBRAIC FUSION. No nonlinearity sits between GEMM1 and GEMM2, so
//        feats = char@(W2t + W1t@W2b) + tok@(W1b@W2b) + (b1@W2b + b2)
//      — ONE K=512 GEMM with precombined weights. Halves tensor FLOPs,
//      deletes the aligned rewrite + all mid-loop barriers + one fp16
//      re-quantization. Precombine done in fp32 by a tiny prep kernel.
//      (R14 reverted: its +32KB smem halved the L1D carveout and slowed
//      the B-fragment LDG stream — smem and L1D trade directly here.)
// ==========================================================================

#define HD       256
#define TILE_M   64
#define LC_SHIFT 14          // Lc = 16384
#define SEQ_S    2048
#define THREADS  256

// dynamic smem layout
#define SM_CHAR   1024                    // 4 chunks x 8KB (char fp16, SW128)
#define SM_TOK    (SM_CHAR + 4 * 8192)    // 4 chunks x 8KB (tok fp16, SW128)
#define SM_PARAM  (SM_TOK  + 4 * 8192)    // be, gamma, beta
#define SM_PART   (SM_PARAM + 3 * HD * 4) // [64][4][2] partial sums
#define SMEM_TOTAL (SM_PART + 64 * 4 * 2 * 4)

#define SWZ(o)   ((o) ^ (((o) >> 3) & 0x70))   // SW128 (A tiles)

// combined fp32 weights [512 k][256 n] and bias (prep output)
__device__ __align__(16) float g_we[512 * 256];
__device__ __align__(16) float g_be[256];
// fragment-major fp16 weight image: [c 0..15][kk 0..1][wn 0..3][g 0..3][lane]
__device__ __align__(16) unsigned char g_wimg[16 * 2 * 4 * 4 * 512];

// ---------------- helpers ----------------
static __device__ __forceinline__ uint32_t smem_u32(const void* p) {
    uint32_t a;
    asm("{ .reg .u64 t; cvta.to.shared.u64 t, %1; cvt.u32.u64 %0, t; }"
        : "=r"(a) : "l"(p));
    return a;
}
static __device__ __forceinline__ uint32_t f2h2(float x, float y) {
    __half2 h = __floats2half2_rn(x, y);
    return *reinterpret_cast<uint32_t*>(&h);
}
static __device__ __forceinline__ void ldsm4(uint32_t* r, uint32_t addr) {
    asm volatile("ldmatrix.sync.aligned.m8n8.x4.shared.b16 {%0,%1,%2,%3}, [%4];"
                 : "=r"(r[0]), "=r"(r[1]), "=r"(r[2]), "=r"(r[3]) : "r"(addr));
}
static __device__ __forceinline__ void mma16816(float* d, const uint32_t* a,
                                                const uint32_t* b) {
    asm volatile(
        "mma.sync.aligned.m16n8k16.row.col.f32.f16.f16.f32 "
        "{%0,%1,%2,%3}, {%4,%5,%6,%7}, {%8,%9}, {%0,%1,%2,%3};"
        : "+f"(d[0]), "+f"(d[1]), "+f"(d[2]), "+f"(d[3])
        : "r"(a[0]), "r"(a[1]), "r"(a[2]), "r"(a[3]), "r"(b[0]), "r"(b[1]));
}
// tanh-formulation GELU: 1 MUFU + ~6 flops
static __device__ __forceinline__ float gelu_t(float x) {
    float u = x * (0.7978845608028654f + 0.03567740814183479f * x * x);
    float t;
    asm("tanh.approx.f32 %0, %1;" : "=f"(t) : "f"(u));
    return 0.5f * x * (1.0f + t);
}

// ---------------- prep 1: combine weights in fp32 ----------------
// g_we[k][n] = (k<256 ? W2[k][n] : 0) + sum_m W1[k][m] * W2[256+m][n]
// g_be[n]    = b2[n] + sum_m b1[m] * W2[256+m][n]
__global__ void prep_comb(const float* __restrict__ W1, const float* __restrict__ b1,
                          const float* __restrict__ W2, const float* __restrict__ b2) {
    const int n = threadIdx.x;
    if (blockIdx.x < 64) {
        const int k0 = blockIdx.x * 8;
        float acc[8];
#pragma unroll
        for (int e = 0; e < 8; e++) acc[e] = 0.f;
        for (int m = 0; m < 256; m++) {
            const float w2v = __ldg(W2 + (256 + m) * 256 + n);
#pragma unroll
            for (int e = 0; e < 8; e++)
                acc[e] += __ldg(W1 + (size_t)(k0 + e) * 256 + m) * w2v;
        }
#pragma unroll
        for (int e = 0; e < 8; e++) {
            const int k = k0 + e;
            const float base = (k < 256) ? __ldg(W2 + (size_t)k * 256 + n) : 0.f;
            g_we[(size_t)k * 256 + n] = base + acc[e];
        }
    } else {
        float acc = 0.f;
        for (int m = 0; m < 256; m++)
            acc += __ldg(b1 + m) * __ldg(W2 + (256 + m) * 256 + n);
        g_be[n] = __ldg(b2 + n) + acc;
    }
}

// ---------------- prep 2: fp32 g_we -> fragment-major fp16 image ----------
__global__ void prep_wimg() {
    int t = blockIdx.x * blockDim.x + threadIdx.x;   // 0..16383 -> one uint4
    int lane = t & 31;
    int g    = (t >> 5) & 3;
    int wn   = (t >> 7) & 3;
    int kk   = (t >> 9) & 1;
    int c    = t >> 10;                              // 0..15
    const int kbase = c * 32 + kk * 16 + (lane & 3) * 2;
    uint4 pk;
    uint32_t v[4];
#pragma unroll
    for (int e = 0; e < 4; e++) {
        const int jh = e >> 1, br = e & 1;
        const int n = wn * 64 + g * 16 + jh * 8 + (lane >> 2);
        const int k = kbase + br * 8;
        v[e] = f2h2(g_we[(size_t)k * 256 + n], g_we[(size_t)(k + 1) * 256 + n]);
    }
    pk.x = v[0]; pk.y = v[1]; pk.z = v[2]; pk.w = v[3];
    reinterpret_cast<uint4*>(g_wimg)[t] = pk;
}

// ---------------- main kernel ----------------
__global__ __launch_bounds__(THREADS, 2)
void syl_main(const float* __restrict__ cemb, const int* __restrict__ alig,
              const float* __restrict__ dec,
              const float* __restrict__ gamma, const float* __restrict__ beta,
              float* __restrict__ outp)
{
    extern __shared__ __align__(1024) unsigned char smem[];
    const uint32_t sb = smem_u32(smem);
    const int tid = threadIdx.x;
    const int wid = tid >> 5, lid = tid & 31;
    const int wm = wid >> 2, wn = wid & 3;        // 2 x 4 warp grid (32m x 64n)
    const size_t r0 = (size_t)blockIdx.x * TILE_M;

    // params -> smem: be, gamma, beta
    float* sp = reinterpret_cast<float*>(smem + SM_PARAM);
    for (int i = tid; i < HD; i += THREADS) {
        sp[i]          = g_be[i];
        sp[HD + i]     = __ldg(gamma + i);
        sp[2 * HD + i] = __ldg(beta + i);
    }

    // B-fragment base for this thread; preload step (c=0, kk=0)
    const unsigned char* bbase = g_wimg + (size_t)(wn * 2048 + lid * 16);
    uint32_t bb[2][16];
#pragma unroll
    for (int g = 0; g < 4; g++)
        *reinterpret_cast<uint4*>(&bb[0][g * 4]) =
            __ldg(reinterpret_cast<const uint4*>(bbase + g * 512));

    // ---- phase L: char + gathered tok tiles, fp32 -> fp16, SW128 ----
    {
        const int c0   = lid * 8;                 // 8 consecutive cols per lane
        const int chnk = c0 >> 6;
        const int cc   = c0 & 63;
        int idxv[8];
#pragma unroll
        for (int i = 0; i < 8; i++)
            idxv[i] = __ldg(alig + r0 + i * 8 + wid);
#pragma unroll
        for (int i = 0; i < 8; i++) {
            const int m = i * 8 + wid;            // warp-per-row: idx uniform per warp
            const size_t rg = r0 + m;
            const float4* cp = reinterpret_cast<const float4*>(cemb + rg * HD + c0);
            float4 a0 = __ldg(cp), a1 = __ldg(cp + 1);
            uint32_t swo = SWZ((uint32_t)(m * 128 + cc * 2));
            uint4 pk;
            pk.x = f2h2(a0.x, a0.y); pk.y = f2h2(a0.z, a0.w);
            pk.z = f2h2(a1.x, a1.y); pk.w = f2h2(a1.z, a1.w);
            *reinterpret_cast<uint4*>(smem + SM_CHAR + chnk * 8192 + swo) = pk;

            const int idraw = idxv[i];
            int idc = idraw < 0 ? 0 : (idraw > (SEQ_S - 1) ? (SEQ_S - 1) : idraw);
            float4 t0 = make_float4(0.f, 0.f, 0.f, 0.f), t1 = t0;
            if (idraw >= 0) {
                const float4* dp = reinterpret_cast<const float4*>(
                    dec + ((rg >> LC_SHIFT) * SEQ_S + (size_t)idc) * HD + c0);
                t0 = __ldg(dp); t1 = __ldg(dp + 1);
            }
            uint4 pt;
            pt.x = f2h2(t0.x, t0.y); pt.y = f2h2(t0.z, t0.w);
            pt.z = f2h2(t1.x, t1.y); pt.w = f2h2(t1.z, t1.w);
            *reinterpret_cast<uint4*>(smem + SM_TOK + chnk * 8192 + swo) = pt;
        }
    }
    __syncthreads();

    // ---- single fused GEMM: 16 K-chunks (K=512), ZERO mid-loop barriers ----
    float acc[2][8][4];
#pragma unroll
    for (int i = 0; i < 2; i++)
#pragma unroll
        for (int j = 0; j < 8; j++)
#pragma unroll
            for (int e = 0; e < 4; e++) acc[i][j][e] = 0.f;

    const uint32_t lxor = (uint32_t)((lid & 7) << 4);       // SW128 XOR (A)
    const uint32_t arow = (uint32_t)(wm * 32 + (lid & 15)); // + i*16
    const uint32_t akh  = (uint32_t)((lid >> 4) * 16);      // k-half byte offset

#pragma unroll 1
    for (int c = 0; c < 16; c++) {
        const int half = c & 1;                   // which 64B half of A's 128B row
        const uint32_t abase = sb + ((c < 8)
            ? (uint32_t)(SM_CHAR + (c >> 1) * 8192)
            : (uint32_t)(SM_TOK + ((c - 8) >> 1) * 8192));
        const unsigned char* bstep = bbase + (size_t)c * 16384;

#pragma unroll
        for (int kk = 0; kk < 2; kk++) {
            // prefetch next K16-step's B fragments into the other buffer
            if (c < 15 || kk == 0) {
                const unsigned char* bn = bstep + (kk == 0 ? 8192 : 16384);
#pragma unroll
                for (int g = 0; g < 4; g++)
                    *reinterpret_cast<uint4*>(&bb[kk ^ 1][g * 4]) =
                        __ldg(reinterpret_cast<const uint4*>(bn + g * 512));
            }
            uint32_t a[2][4];
#pragma unroll
            for (int i = 0; i < 2; i++) {
                uint32_t addr = abase + (arow + i * 16) * 128
                              + (((uint32_t)(half * 64 + kk * 32) + akh) ^ lxor);
                ldsm4(a[i], addr);
            }
#pragma unroll
            for (int i = 0; i < 2; i++)
#pragma unroll
                for (int j = 0; j < 8; j++)
                    mma16816(acc[i][j], a[i], &bb[kk][j * 2]);
        }
    }

    // ---- register-resident epilogue: +be, LN, GELU, +char (char from smem) ----
    {
        const float* bes = sp;                    // combined bias
        float* P = reinterpret_cast<float*>(smem + SM_PART);   // [64][4][2]
#pragma unroll
        for (int i = 0; i < 2; i++) {
            float sA = 0.f, qA = 0.f, sB = 0.f, qB = 0.f;
#pragma unroll
            for (int j = 0; j < 8; j++) {
                const int n = wn * 64 + j * 8 + (lid & 3) * 2;
                float f0 = acc[i][j][0] + bes[n];
                float f1 = acc[i][j][1] + bes[n + 1];
                float f2 = acc[i][j][2] + bes[n];
                float f3 = acc[i][j][3] + bes[n + 1];
                acc[i][j][0] = f0; acc[i][j][1] = f1;
                acc[i][j][2] = f2; acc[i][j][3] = f3;
                sA += f0 + f1; qA += f0 * f0 + f1 * f1;
                sB += f2 + f3; qB += f2 * f2 + f3 * f3;
            }
            sA += __shfl_xor_sync(0xffffffffu, sA, 1);
            qA += __shfl_xor_sync(0xffffffffu, qA, 1);
            sB += __shfl_xor_sync(0xffffffffu, sB, 1);
            qB += __shfl_xor_sync(0xffffffffu, qB, 1);
            sA += __shfl_xor_sync(0xffffffffu, sA, 2);
            qA += __shfl_xor_sync(0xffffffffu, qA, 2);
            sB += __shfl_xor_sync(0xffffffffu, sB, 2);
            qB += __shfl_xor_sync(0xffffffffu, qB, 2);
            if ((lid & 3) == 0) {
                const int rA = wm * 32 + i * 16 + (lid >> 2);
                const int rB = rA + 8;
                P[rA * 8 + wn * 2 + 0] = sA; P[rA * 8 + wn * 2 + 1] = qA;
                P[rB * 8 + wn * 2 + 0] = sB; P[rB * 8 + wn * 2 + 1] = qB;
            }
        }
        __syncthreads();

        const float* gms = sp + HD;
        const float* bts = sp + 2 * HD;
#pragma unroll
        for (int i = 0; i < 2; i++) {
            const int rA = wm * 32 + i * 16 + (lid >> 2);
            const int rB = rA + 8;
            float2 pa0 = *reinterpret_cast<const float2*>(P + rA * 8 + 0);
            float2 pa1 = *reinterpret_cast<const float2*>(P + rA * 8 + 2);
            float2 pa2 = *reinterpret_cast<const float2*>(P + rA * 8 + 4);
            float2 pa3 = *reinterpret_cast<const float2*>(P + rA * 8 + 6);
            float2 pb0 = *reinterpret_cast<const float2*>(P + rB * 8 + 0);
            float2 pb1 = *reinterpret_cast<const float2*>(P + rB * 8 + 2);
            float2 pb2 = *reinterpret_cast<const float2*>(P + rB * 8 + 4);
            float2 pb3 = *reinterpret_cast<const float2*>(P + rB * 8 + 6);
            float sA = pa0.x + pa1.x + pa2.x + pa3.x;
            float qA = pa0.y + pa1.y + pa2.y + pa3.y;
            float sB = pb0.x + pb1.x + pb2.x + pb3.x;
            float qB = pb0.y + pb1.y + pb2.y + pb3.y;
            const float muA = sA * (1.0f / HD);
            const float rsA = rsqrtf(qA * (1.0f / HD) - muA * muA + 1e-5f);
            const float muB = sB * (1.0f / HD);
            const float rsB = rsqrtf(qB * (1.0f / HD) - muB * muB + 1e-5f);
            const size_t gA = (r0 + rA) * HD, gB = (r0 + rB) * HD;
            const uint32_t rxA = ((uint32_t)(rA & 7)) << 4;   // rB&7 == rA&7
#pragma unroll
            for (int j = 0; j < 8; j++) {
                const int cl = j * 8 + (lid & 3) * 2;
                const int n = wn * 64 + cl;
                const float g0 = gms[n], g1 = gms[n + 1];
                const float t0 = bts[n], t1 = bts[n + 1];
                const uint32_t co = ((uint32_t)(cl * 2)) ^ rxA;
                __half2 hcA = *reinterpret_cast<const __half2*>(
                    smem + SM_CHAR + wn * 8192 + rA * 128 + co);
                __half2 hcB = *reinterpret_cast<const __half2*>(
                    smem + SM_CHAR + wn * 8192 + rB * 128 + co);
                float2 chA = __half22float2(hcA);
                float2 chB = __half22float2(hcB);
                float hA0 = (acc[i][j][0] - muA) * rsA * g0 + t0;
                float hA1 = (acc[i][j][1] - muA) * rsA * g1 + t1;
                float hB0 = (acc[i][j][2] - muB) * rsB * g0 + t0;
                float hB1 = (acc[i][j][3] - muB) * rsB * g1 + t1;
                float2 oA, oB;
                oA.x = chA.x + gelu_t(hA0);
                oA.y = chA.y + gelu_t(hA1);
                oB.x = chB.x + gelu_t(hB0);
                oB.y = chB.y + gelu_t(hB1);
                *reinterpret_cast<float2*>(outp + gA + n) = oA;
                *reinterpret_cast<float2*>(outp + gB + n) = oB;
            }
        }
    }
}

// ---------------- launch ----------------
extern "C" void kernel_launch(void* const* d_in, const int* in_sizes, int n_in,
                              void* d_out, int out_size) {
    const float* cemb  = (const float*)d_in[0];
    const int*   alig  = (const int*)d_in[1];
    const float* dec   = (const float*)d_in[2];
    const float* W1    = (const float*)d_in[3];
    const float* b1    = (const float*)d_in[4];
    const float* W2    = (const float*)d_in[5];
    const float* b2    = (const float*)d_in[6];
    const float* gamma = (const float*)d_in[7];
    const float* beta  = (const float*)d_in[8];
    float* outp = (float*)d_out;

    prep_comb<<<65, 256>>>(W1, b1, W2, b2);
    prep_wimg<<<64, 256>>>();

    cudaFuncSetAttribute(syl_main, cudaFuncAttributeMaxDynamicSharedMemorySize, SMEM_TOTAL);
    const int rows  = in_sizes[0] / HD;     // B * Lc = 131072 (from char elem count)
    const int tiles = rows / TILE_M;        // 2048
    syl_main<<<tiles, THREADS, SMEM_TOTAL>>>(cemb, alig, dec, gamma, beta, outp);
}

// round 16
// speedup vs baseline: 1.4414x; 1.2976x over previous
#include <cuda_runtime.h>
#include <cuda_fp16.h>
#include <stdint.h>

// ==========================================================================
// SyllableProcessor on GB300 (sm_103 base target — tcgen05 unavailable).
//   out = char + GELU(LN( [char, (comb@W1+b1)] @ W2 + b2 )),  comb=[char,gather]
// R16: R15 fused-GEMM champion with the prep kernel rewritten for
//      parallelism. R15's profile showed prep_comb = 67us of the 188.8us
//      total (65 blocks, scalar serial loop, issue 8.3%) — the main kernel
//      is ~120us. New prep: 128 blocks x 256 thr, W1 staged in smem and
//      read as float4, coalesced W2 stream -> ~3us. Main kernel UNCHANGED.
// ==========================================================================

#define HD       256
#define TILE_M   64
#define LC_SHIFT 14          // Lc = 16384
#define SEQ_S    2048
#define THREADS  256

// dynamic smem layout
#define SM_CHAR   1024                    // 4 chunks x 8KB (char fp16, SW128)
#define SM_TOK    (SM_CHAR + 4 * 8192)    // 4 chunks x 8KB (tok fp16, SW128)
#define SM_PARAM  (SM_TOK  + 4 * 8192)    // be, gamma, beta
#define SM_PART   (SM_PARAM + 3 * HD * 4) // [64][4][2] partial sums
#define SMEM_TOTAL (SM_PART + 64 * 4 * 2 * 4)

#define SWZ(o)   ((o) ^ (((o) >> 3) & 0x70))   // SW128 (A tiles)

// combined fp32 weights [512 k][256 n] and bias (prep output)
__device__ __align__(16) float g_we[512 * 256];
__device__ __align__(16) float g_be[256];
// fragment-major fp16 weight image: [c 0..15][kk 0..1][wn 0..3][g 0..3][lane]
__device__ __align__(16) unsigned char g_wimg[16 * 2 * 4 * 4 * 512];

// ---------------- helpers ----------------
static __device__ __forceinline__ uint32_t smem_u32(const void* p) {
    uint32_t a;
    asm("{ .reg .u64 t; cvta.to.shared.u64 t, %1; cvt.u32.u64 %0, t; }"
        : "=r"(a) : "l"(p));
    return a;
}
static __device__ __forceinline__ uint32_t f2h2(float x, float y) {
    __half2 h = __floats2half2_rn(x, y);
    return *reinterpret_cast<uint32_t*>(&h);
}
static __device__ __forceinline__ void ldsm4(uint32_t* r, uint32_t addr) {
    asm volatile("ldmatrix.sync.aligned.m8n8.x4.shared.b16 {%0,%1,%2,%3}, [%4];"
                 : "=r"(r[0]), "=r"(r[1]), "=r"(r[2]), "=r"(r[3]) : "r"(addr));
}
static __device__ __forceinline__ void mma16816(float* d, const uint32_t* a,
                                                const uint32_t* b) {
    asm volatile(
        "mma.sync.aligned.m16n8k16.row.col.f32.f16.f16.f32 "
        "{%0,%1,%2,%3}, {%4,%5,%6,%7}, {%8,%9}, {%0,%1,%2,%3};"
        : "+f"(d[0]), "+f"(d[1]), "+f"(d[2]), "+f"(d[3])
        : "r"(a[0]), "r"(a[1]), "r"(a[2]), "r"(a[3]), "r"(b[0]), "r"(b[1]));
}
// tanh-formulation GELU: 1 MUFU + ~6 flops
static __device__ __forceinline__ float gelu_t(float x) {
    float u = x * (0.7978845608028654f + 0.03567740814183479f * x * x);
    float t;
    asm("tanh.approx.f32 %0, %1;" : "=f"(t) : "f"(u));
    return 0.5f * x * (1.0f + t);
}

// ---------------- prep 1: combine weights in fp32 (parallel) ----------------
// g_we[k][n] = (k<256 ? W2[k][n] : 0) + sum_m W1[k][m] * W2[256+m][n]
// g_be[n]    = b2[n] + sum_m b1[m] * W2[256+m][n]
// 128 blocks x 4 k-rows, 256 threads (one n each); W1 rows staged in smem.
__global__ void prep_comb(const float* __restrict__ W1, const float* __restrict__ b1,
                          const float* __restrict__ W2, const float* __restrict__ b2) {
    __shared__ __align__(16) float sW1[4 * 256];
    const int n = threadIdx.x;
    if (blockIdx.x < 128) {
        const int k0 = blockIdx.x * 4;
#pragma unroll
        for (int e = 0; e < 4; e++)
            sW1[e * 256 + n] = __ldg(W1 + (size_t)(k0 + e) * 256 + n);
        __syncthreads();
        float acc[4] = {0.f, 0.f, 0.f, 0.f};
#pragma unroll 4
        for (int mq = 0; mq < 64; mq++) {
            float4 w1q[4];
#pragma unroll
            for (int e = 0; e < 4; e++)
                w1q[e] = *reinterpret_cast<const float4*>(sW1 + e * 256 + mq * 4);
            const float* w1s = reinterpret_cast<const float*>(w1q);  // [e][mm]
#pragma unroll
            for (int mm = 0; mm < 4; mm++) {
                const int m = mq * 4 + mm;
                const float w2v = __ldg(W2 + (size_t)(256 + m) * 256 + n);
#pragma unroll
                for (int e = 0; e < 4; e++)
                    acc[e] += w1s[e * 4 + mm] * w2v;
            }
        }
#pragma unroll
        for (int e = 0; e < 4; e++) {
            const int k = k0 + e;
            const float base = (k < 256) ? __ldg(W2 + (size_t)k * 256 + n) : 0.f;
            g_we[(size_t)k * 256 + n] = base + acc[e];
        }
    } else {
        float acc = 0.f;
        for (int m = 0; m < 256; m++)
            acc += __ldg(b1 + m) * __ldg(W2 + (size_t)(256 + m) * 256 + n);
        g_be[n] = __ldg(b2 + n) + acc;
    }
}

// ---------------- prep 2: fp32 g_we -> fragment-major fp16 image ----------
__global__ void prep_wimg() {
    int t = blockIdx.x * blockDim.x + threadIdx.x;   // 0..16383 -> one uint4
    int lane = t & 31;
    int g    = (t >> 5) & 3;
    int wn   = (t >> 7) & 3;
    int kk   = (t >> 9) & 1;
    int c    = t >> 10;                              // 0..15
    const int kbase = c * 32 + kk * 16 + (lane & 3) * 2;
    uint4 pk;
    uint32_t v[4];
#pragma unroll
    for (int e = 0; e < 4; e++) {
        const int jh = e >> 1, br = e & 1;
        const int n = wn * 64 + g * 16 + jh * 8 + (lane >> 2);
        const int k = kbase + br * 8;
        v[e] = f2h2(g_we[(size_t)k * 256 + n], g_we[(size_t)(k + 1) * 256 + n]);
    }
    pk.x = v[0]; pk.y = v[1]; pk.z = v[2]; pk.w = v[3];
    reinterpret_cast<uint4*>(g_wimg)[t] = pk;
}

// ---------------- main kernel (UNCHANGED from R15) ----------------
__global__ __launch_bounds__(THREADS, 2)
void syl_main(const float* __restrict__ cemb, const int* __restrict__ alig,
              const float* __restrict__ dec,
              const float* __restrict__ gamma, const float* __restrict__ beta,
              float* __restrict__ outp)
{
    extern __shared__ __align__(1024) unsigned char smem[];
    const uint32_t sb = smem_u32(smem);
    const int tid = threadIdx.x;
    const int wid = tid >> 5, lid = tid & 31;
    const int wm = wid >> 2, wn = wid & 3;        // 2 x 4 warp grid (32m x 64n)
    const size_t r0 = (size_t)blockIdx.x * TILE_M;

    // params -> smem: be, gamma, beta
    float* sp = reinterpret_cast<float*>(smem + SM_PARAM);
    for (int i = tid; i < HD; i += THREADS) {
        sp[i]          = g_be[i];
        sp[HD + i]     = __ldg(gamma + i);
        sp[2 * HD + i] = __ldg(beta + i);
    }

    // B-fragment base for this thread; preload step (c=0, kk=0)
    const unsigned char* bbase = g_wimg + (size_t)(wn * 2048 + lid * 16);
    uint32_t bb[2][16];
#pragma unroll
    for (int g = 0; g < 4; g++)
        *reinterpret_cast<uint4*>(&bb[0][g * 4]) =
            __ldg(reinterpret_cast<const uint4*>(bbase + g * 512));

    // ---- phase L: char + gathered tok tiles, fp32 -> fp16, SW128 ----
    {
        const int c0   = lid * 8;                 // 8 consecutive cols per lane
        const int chnk = c0 >> 6;
        const int cc   = c0 & 63;
        int idxv[8];
#pragma unroll
        for (int i = 0; i < 8; i++)
            idxv[i] = __ldg(alig + r0 + i * 8 + wid);
#pragma unroll
        for (int i = 0; i < 8; i++) {
            const int m = i * 8 + wid;            // warp-per-row: idx uniform per warp
            const size_t rg = r0 + m;
            const float4* cp = reinterpret_cast<const float4*>(cemb + rg * HD + c0);
            float4 a0 = __ldg(cp), a1 = __ldg(cp + 1);
            uint32_t swo = SWZ((uint32_t)(m * 128 + cc * 2));
            uint4 pk;
            pk.x = f2h2(a0.x, a0.y); pk.y = f2h2(a0.z, a0.w);
            pk.z = f2h2(a1.x, a1.y); pk.w = f2h2(a1.z, a1.w);
            *reinterpret_cast<uint4*>(smem + SM_CHAR + chnk * 8192 + swo) = pk;

            const int idraw = idxv[i];
            int idc = idraw < 0 ? 0 : (idraw > (SEQ_S - 1) ? (SEQ_S - 1) : idraw);
            float4 t0 = make_float4(0.f, 0.f, 0.f, 0.f), t1 = t0;
            if (idraw >= 0) {
                const float4* dp = reinterpret_cast<const float4*>(
                    dec + ((rg >> LC_SHIFT) * SEQ_S + (size_t)idc) * HD + c0);
                t0 = __ldg(dp); t1 = __ldg(dp + 1);
            }
            uint4 pt;
            pt.x = f2h2(t0.x, t0.y); pt.y = f2h2(t0.z, t0.w);
            pt.z = f2h2(t1.x, t1.y); pt.w = f2h2(t1.z, t1.w);
            *reinterpret_cast<uint4*>(smem + SM_TOK + chnk * 8192 + swo) = pt;
        }
    }
    __syncthreads();

    // ---- single fused GEMM: 16 K-chunks (K=512), ZERO mid-loop barriers ----
    float acc[2][8][4];
#pragma unroll
    for (int i = 0; i < 2; i++)
#pragma unroll
        for (int j = 0; j < 8; j++)
#pragma unroll
            for (int e = 0; e < 4; e++) acc[i][j][e] = 0.f;

    const uint32_t lxor = (uint32_t)((lid & 7) << 4);       // SW128 XOR (A)
    const uint32_t arow = (uint32_t)(wm * 32 + (lid & 15)); // + i*16
    const uint32_t akh  = (uint32_t)((lid >> 4) * 16);      // k-half byte offset

#pragma unroll 1
    for (int c = 0; c < 16; c++) {
        const int half = c & 1;                   // which 64B half of A's 128B row
        const uint32_t abase = sb + ((c < 8)
            ? (uint32_t)(SM_CHAR + (c >> 1) * 8192)
            : (uint32_t)(SM_TOK + ((c - 8) >> 1) * 8192));
        const unsigned char* bstep = bbase + (size_t)c * 16384;

#pragma unroll
        for (int kk = 0; kk < 2; kk++) {
            // prefetch next K16-step's B fragments into the other buffer
            if (c < 15 || kk == 0) {
                const unsigned char* bn = bstep + (kk == 0 ? 8192 : 16384);
#pragma unroll
                for (int g = 0; g < 4; g++)
                    *reinterpret_cast<uint4*>(&bb[kk ^ 1][g * 4]) =
                        __ldg(reinterpret_cast<const uint4*>(bn + g * 512));
            }
            uint32_t a[2][4];
#pragma unroll
            for (int i = 0; i < 2; i++) {
                uint32_t addr = abase + (arow + i * 16) * 128
                              + (((uint32_t)(half * 64 + kk * 32) + akh) ^ lxor);
                ldsm4(a[i], addr);
            }
#pragma unroll
            for (int i = 0; i < 2; i++)
#pragma unroll
                for (int j = 0; j < 8; j++)
                    mma16816(acc[i][j], a[i], &bb[kk][j * 2]);
        }
    }

    // ---- register-resident epilogue: +be, LN, GELU, +char (char from smem) ----
    {
        const float* bes = sp;                    // combined bias
        float* P = reinterpret_cast<float*>(smem + SM_PART);   // [64][4][2]
#pragma unroll
        for (int i = 0; i < 2; i++) {
            float sA = 0.f, qA = 0.f, sB = 0.f, qB = 0.f;
#pragma unroll
            for (int j = 0; j < 8; j++) {
                const int n = wn * 64 + j * 8 + (lid & 3) * 2;
                float f0 = acc[i][j][0] + bes[n];
                float f1 = acc[i][j][1] + bes[n + 1];
                float f2 = acc[i][j][2] + bes[n];
                float f3 = acc[i][j][3] + bes[n + 1];
                acc[i][j][0] = f0; acc[i][j][1] = f1;
                acc[i][j][2] = f2; acc[i][j][3] = f3;
                sA += f0 + f1; qA += f0 * f0 + f1 * f1;
                sB += f2 + f3; qB += f2 * f2 + f3 * f3;
            }
            sA += __shfl_xor_sync(0xffffffffu, sA, 1);
            qA += __shfl_xor_sync(0xffffffffu, qA, 1);
            sB += __shfl_xor_sync(0xffffffffu, sB, 1);
            qB += __shfl_xor_sync(0xffffffffu, qB, 1);
            sA += __shfl_xor_sync(0xffffffffu, sA, 2);
            qA += __shfl_xor_sync(0xffffffffu, qA, 2);
            sB += __shfl_xor_sync(0xffffffffu, sB, 2);
            qB += __shfl_xor_sync(0xffffffffu, qB, 2);
            if ((lid & 3) == 0) {
                const int rA = wm * 32 + i * 16 + (lid >> 2);
                const int rB = rA + 8;
                P[rA * 8 + wn * 2 + 0] = sA; P[rA * 8 + wn * 2 + 1] = qA;
                P[rB * 8 + wn * 2 + 0] = sB; P[rB * 8 + wn * 2 + 1] = qB;
            }
        }
        __syncthreads();

        const float* gms = sp + HD;
        const float* bts = sp + 2 * HD;
#pragma unroll
        for (int i = 0; i < 2; i++) {
            const int rA = wm * 32 + i * 16 + (lid >> 2);
            const int rB = rA + 8;
            float2 pa0 = *reinterpret_cast<const float2*>(P + rA * 8 + 0);
            float2 pa1 = *reinterpret_cast<const float2*>(P + rA * 8 + 2);
            float2 pa2 = *reinterpret_cast<const float2*>(P + rA * 8 + 4);
            float2 pa3 = *reinterpret_cast<const float2*>(P + rA * 8 + 6);
            float2 pb0 = *reinterpret_cast<const float2*>(P + rB * 8 + 0);
            float2 pb1 = *reinterpret_cast<const float2*>(P + rB * 8 + 2);
            float2 pb2 = *reinterpret_cast<const float2*>(P + rB * 8 + 4);
            float2 pb3 = *reinterpret_cast<const float2*>(P + rB * 8 + 6);
            float sA = pa0.x + pa1.x + pa2.x + pa3.x;
            float qA = pa0.y + pa1.y + pa2.y + pa3.y;
            float sB = pb0.x + pb1.x + pb2.x + pb3.x;
            float qB = pb0.y + pb1.y + pb2.y + pb3.y;
            const float muA = sA * (1.0f / HD);
            const float rsA = rsqrtf(qA * (1.0f / HD) - muA * muA + 1e-5f);
            const float muB = sB * (1.0f / HD);
            const float rsB = rsqrtf(qB * (1.0f / HD) - muB * muB + 1e-5f);
            const size_t gA = (r0 + rA) * HD, gB = (r0 + rB) * HD;
            const uint32_t rxA = ((uint32_t)(rA & 7)) << 4;   // rB&7 == rA&7
#pragma unroll
            for (int j = 0; j < 8; j++) {
                const int cl = j * 8 + (lid & 3) * 2;
                const int n = wn * 64 + cl;
                const float g0 = gms[n], g1 = gms[n + 1];
                const float t0 = bts[n], t1 = bts[n + 1];
                const uint32_t co = ((uint32_t)(cl * 2)) ^ rxA;
                __half2 hcA = *reinterpret_cast<const __half2*>(
                    smem + SM_CHAR + wn * 8192 + rA * 128 + co);
                __half2 hcB = *reinterpret_cast<const __half2*>(
                    smem + SM_CHAR + wn * 8192 + rB * 128 + co);
                float2 chA = __half22float2(hcA);
                float2 chB = __half22float2(hcB);
                float hA0 = (acc[i][j][0] - muA) * rsA * g0 + t0;
                float hA1 = (acc[i][j][1] - muA) * rsA * g1 + t1;
                float hB0 = (acc[i][j][2] - muB) * rsB * g0 + t0;
                float hB1 = (acc[i][j][3] - muB) * rsB * g1 + t1;
                float2 oA, oB;
                oA.x = chA.x + gelu_t(hA0);
                oA.y = chA.y + gelu_t(hA1);
                oB.x = chB.x + gelu_t(hB0);
                oB.y = chB.y + gelu_t(hB1);
                *reinterpret_cast<float2*>(outp + gA + n) = oA;
                *reinterpret_cast<float2*>(outp + gB + n) = oB;
            }
        }
    }
}

// ---------------- launch ----------------
extern "C" void kernel_launch(void* const* d_in, const int* in_sizes, int n_in,
                              void* d_out, int out_size) {
    const float* cemb  = (const float*)d_in[0];
    const int*   alig  = (const int*)d_in[1];
    const float* dec   = (const float*)d_in[2];
    const float* W1    = (const float*)d_in[3];
    const float* b1    = (const float*)d_in[4];
    const float* W2    = (const float*)d_in[5];
    const float* b2    = (const float*)d_in[6];
    const float* gamma = (const float*)d_in[7];
    const float* beta  = (const float*)d_in[8];
    float* outp = (float*)d_out;

    prep_comb<<<129, 256>>>(W1, b1, W2, b2);
    prep_wimg<<<64, 256>>>();

    cudaFuncSetAttribute(syl_main, cudaFuncAttributeMaxDynamicSharedMemorySize, SMEM_TOTAL);
    const int rows  = in_sizes[0] / HD;     // B * Lc = 131072 (from char elem count)
    const int tiles = rows / TILE_M;        // 2048
    syl_main<<<tiles, THREADS, SMEM_TOTAL>>>(cemb, alig, dec, gamma, beta, outp);
}

// round 17
// speedup vs baseline: 1.4721x; 1.0213x over previous
#include <cuda_runtime.h>
#include <cuda_fp16.h>
#include <stdint.h>

// ==========================================================================
// SyllableProcessor on GB300 (sm_103 base target — tcgen05 unavailable).
//   out = char + GELU(LN( [char, (comb@W1+b1)] @ W2 + b2 )),  comb=[char,gather]
// R17: R16 champion, prep_comb re-parallelized AGAIN. R16 profile: prep
//      still 23.6us (128 blocks, <1 block/SM, latency-bound). New prep:
//      256 blocks x 2 k-rows, flat m-loop unrolled x8 (8 outstanding LDGs),
//      ~16 warps/SM -> predicted 4-6us. Main kernel UNCHANGED (~120us).
// ==========================================================================

#define HD       256
#define TILE_M   64
#define LC_SHIFT 14          // Lc = 16384
#define SEQ_S    2048
#define THREADS  256

// dynamic smem layout
#define SM_CHAR   1024                    // 4 chunks x 8KB (char fp16, SW128)
#define SM_TOK    (SM_CHAR + 4 * 8192)    // 4 chunks x 8KB (tok fp16, SW128)
#define SM_PARAM  (SM_TOK  + 4 * 8192)    // be, gamma, beta
#define SM_PART   (SM_PARAM + 3 * HD * 4) // [64][4][2] partial sums
#define SMEM_TOTAL (SM_PART + 64 * 4 * 2 * 4)

#define SWZ(o)   ((o) ^ (((o) >> 3) & 0x70))   // SW128 (A tiles)

// combined fp32 weights [512 k][256 n] and bias (prep output)
__device__ __align__(16) float g_we[512 * 256];
__device__ __align__(16) float g_be[256];
// fragment-major fp16 weight image: [c 0..15][kk 0..1][wn 0..3][g 0..3][lane]
__device__ __align__(16) unsigned char g_wimg[16 * 2 * 4 * 4 * 512];

// ---------------- helpers ----------------
static __device__ __forceinline__ uint32_t smem_u32(const void* p) {
    uint32_t a;
    asm("{ .reg .u64 t; cvta.to.shared.u64 t, %1; cvt.u32.u64 %0, t; }"
        : "=r"(a) : "l"(p));
    return a;
}
static __device__ __forceinline__ uint32_t f2h2(float x, float y) {
    __half2 h = __floats2half2_rn(x, y);
    return *reinterpret_cast<uint32_t*>(&h);
}
static __device__ __forceinline__ void ldsm4(uint32_t* r, uint32_t addr) {
    asm volatile("ldmatrix.sync.aligned.m8n8.x4.shared.b16 {%0,%1,%2,%3}, [%4];"
                 : "=r"(r[0]), "=r"(r[1]), "=r"(r[2]), "=r"(r[3]) : "r"(addr));
}
static __device__ __forceinline__ void mma16816(float* d, const uint32_t* a,
                                                const uint32_t* b) {
    asm volatile(
        "mma.sync.aligned.m16n8k16.row.col.f32.f16.f16.f32 "
        "{%0,%1,%2,%3}, {%4,%5,%6,%7}, {%8,%9}, {%0,%1,%2,%3};"
        : "+f"(d[0]), "+f"(d[1]), "+f"(d[2]), "+f"(d[3])
        : "r"(a[0]), "r"(a[1]), "r"(a[2]), "r"(a[3]), "r"(b[0]), "r"(b[1]));
}
// tanh-formulation GELU: 1 MUFU + ~6 flops
static __device__ __forceinline__ float gelu_t(float x) {
    float u = x * (0.7978845608028654f + 0.03567740814183479f * x * x);
    float t;
    asm("tanh.approx.f32 %0, %1;" : "=f"(t) : "f"(u));
    return 0.5f * x * (1.0f + t);
}

// ---------------- prep 1: combine weights in fp32 (highly parallel) --------
// g_we[k][n] = (k<256 ? W2[k][n] : 0) + sum_m W1[k][m] * W2[256+m][n]
// g_be[n]    = b2[n] + sum_m b1[m] * W2[256+m][n]
// 256 blocks x 2 k-rows, 256 threads (one n each); W1 rows staged in smem
// (broadcast reads); flat m-loop unrolled x8 for deep LDG batching.
__global__ void prep_comb(const float* __restrict__ W1, const float* __restrict__ b1,
                          const float* __restrict__ W2, const float* __restrict__ b2) {
    __shared__ __align__(16) float sW1[2 * 256];
    const int n = threadIdx.x;
    if (blockIdx.x < 256) {
        const int k0 = blockIdx.x * 2;
        sW1[n]       = __ldg(W1 + (size_t)k0 * 256 + n);
        sW1[256 + n] = __ldg(W1 + (size_t)(k0 + 1) * 256 + n);
        __syncthreads();
        float acc0 = 0.f, acc1 = 0.f;
#pragma unroll 8
        for (int m = 0; m < 256; m++) {
            const float w2v = __ldg(W2 + (size_t)(256 + m) * 256 + n);
            acc0 += sW1[m] * w2v;
            acc1 += sW1[256 + m] * w2v;
        }
        {
            const float base0 = (k0 < 256) ? __ldg(W2 + (size_t)k0 * 256 + n) : 0.f;
            const float base1 = (k0 + 1 < 256) ? __ldg(W2 + (size_t)(k0 + 1) * 256 + n) : 0.f;
            g_we[(size_t)k0 * 256 + n]       = base0 + acc0;
            g_we[(size_t)(k0 + 1) * 256 + n] = base1 + acc1;
        }
    } else {
        float acc = 0.f;
#pragma unroll 8
        for (int m = 0; m < 256; m++)
            acc += __ldg(b1 + m) * __ldg(W2 + (size_t)(256 + m) * 256 + n);
        g_be[n] = __ldg(b2 + n) + acc;
    }
}

// ---------------- prep 2: fp32 g_we -> fragment-major fp16 image ----------
__global__ void prep_wimg() {
    int t = blockIdx.x * blockDim.x + threadIdx.x;   // 0..16383 -> one uint4
    int lane = t & 31;
    int g    = (t >> 5) & 3;
    int wn   = (t >> 7) & 3;
    int kk   = (t >> 9) & 1;
    int c    = t >> 10;                              // 0..15
    const int kbase = c * 32 + kk * 16 + (lane & 3) * 2;
    uint4 pk;
    uint32_t v[4];
#pragma unroll
    for (int e = 0; e < 4; e++) {
        const int jh = e >> 1, br = e & 1;
        const int n = wn * 64 + g * 16 + jh * 8 + (lane >> 2);
        const int k = kbase + br * 8;
        v[e] = f2h2(g_we[(size_t)k * 256 + n], g_we[(size_t)(k + 1) * 256 + n]);
    }
    pk.x = v[0]; pk.y = v[1]; pk.z = v[2]; pk.w = v[3];
    reinterpret_cast<uint4*>(g_wimg)[t] = pk;
}

// ---------------- main kernel (UNCHANGED from R16) ----------------
__global__ __launch_bounds__(THREADS, 2)
void syl_main(const float* __restrict__ cemb, const int* __restrict__ alig,
              const float* __restrict__ dec,
              const float* __restrict__ gamma, const float* __restrict__ beta,
              float* __restrict__ outp)
{
    extern __shared__ __align__(1024) unsigned char smem[];
    const uint32_t sb = smem_u32(smem);
    const int tid = threadIdx.x;
    const int wid = tid >> 5, lid = tid & 31;
    const int wm = wid >> 2, wn = wid & 3;        // 2 x 4 warp grid (32m x 64n)
    const size_t r0 = (size_t)blockIdx.x * TILE_M;

    // params -> smem: be, gamma, beta
    float* sp = reinterpret_cast<float*>(smem + SM_PARAM);
    for (int i = tid; i < HD; i += THREADS) {
        sp[i]          = g_be[i];
        sp[HD + i]     = __ldg(gamma + i);
        sp[2 * HD + i] = __ldg(beta + i);
    }

    // B-fragment base for this thread; preload step (c=0, kk=0)
    const unsigned char* bbase = g_wimg + (size_t)(wn * 2048 + lid * 16);
    uint32_t bb[2][16];
#pragma unroll
    for (int g = 0; g < 4; g++)
        *reinterpret_cast<uint4*>(&bb[0][g * 4]) =
            __ldg(reinterpret_cast<const uint4*>(bbase + g * 512));

    // ---- phase L: char + gathered tok tiles, fp32 -> fp16, SW128 ----
    {
        const int c0   = lid * 8;                 // 8 consecutive cols per lane
        const int chnk = c0 >> 6;
        const int cc   = c0 & 63;
        int idxv[8];
#pragma unroll
        for (int i = 0; i < 8; i++)
            idxv[i] = __ldg(alig + r0 + i * 8 + wid);
#pragma unroll
        for (int i = 0; i < 8; i++) {
            const int m = i * 8 + wid;            // warp-per-row: idx uniform per warp
            const size_t rg = r0 + m;
            const float4* cp = reinterpret_cast<const float4*>(cemb + rg * HD + c0);
            float4 a0 = __ldg(cp), a1 = __ldg(cp + 1);
            uint32_t swo = SWZ((uint32_t)(m * 128 + cc * 2));
            uint4 pk;
            pk.x = f2h2(a0.x, a0.y); pk.y = f2h2(a0.z, a0.w);
            pk.z = f2h2(a1.x, a1.y); pk.w = f2h2(a1.z, a1.w);
            *reinterpret_cast<uint4*>(smem + SM_CHAR + chnk * 8192 + swo) = pk;

            const int idraw = idxv[i];
            int idc = idraw < 0 ? 0 : (idraw > (SEQ_S - 1) ? (SEQ_S - 1) : idraw);
            float4 t0 = make_float4(0.f, 0.f, 0.f, 0.f), t1 = t0;
            if (idraw >= 0) {
                const float4* dp = reinterpret_cast<const float4*>(
                    dec + ((rg >> LC_SHIFT) * SEQ_S + (size_t)idc) * HD + c0);
                t0 = __ldg(dp); t1 = __ldg(dp + 1);
            }
            uint4 pt;
            pt.x = f2h2(t0.x, t0.y); pt.y = f2h2(t0.z, t0.w);
            pt.z = f2h2(t1.x, t1.y); pt.w = f2h2(t1.z, t1.w);
            *reinterpret_cast<uint4*>(smem + SM_TOK + chnk * 8192 + swo) = pt;
        }
    }
    __syncthreads();

    // ---- single fused GEMM: 16 K-chunks (K=512), ZERO mid-loop barriers ----
    float acc[2][8][4];
#pragma unroll
    for (int i = 0; i < 2; i++)
#pragma unroll
        for (int j = 0; j < 8; j++)
#pragma unroll
            for (int e = 0; e < 4; e++) acc[i][j][e] = 0.f;

    const uint32_t lxor = (uint32_t)((lid & 7) << 4);       // SW128 XOR (A)
    const uint32_t arow = (uint32_t)(wm * 32 + (lid & 15)); // + i*16
    const uint32_t akh  = (uint32_t)((lid >> 4) * 16);      // k-half byte offset

#pragma unroll 1
    for (int c = 0; c < 16; c++) {
        const int half = c & 1;                   // which 64B half of A's 128B row
        const uint32_t abase = sb + ((c < 8)
            ? (uint32_t)(SM_CHAR + (c >> 1) * 8192)
            : (uint32_t)(SM_TOK + ((c - 8) >> 1) * 8192));
        const unsigned char* bstep = bbase + (size_t)c * 16384;

#pragma unroll
        for (int kk = 0; kk < 2; kk++) {
            // prefetch next K16-step's B fragments into the other buffer
            if (c < 15 || kk == 0) {
                const unsigned char* bn = bstep + (kk == 0 ? 8192 : 16384);
#pragma unroll
                for (int g = 0; g < 4; g++)
                    *reinterpret_cast<uint4*>(&bb[kk ^ 1][g * 4]) =
                        __ldg(reinterpret_cast<const uint4*>(bn + g * 512));
            }
            uint32_t a[2][4];
#pragma unroll
            for (int i = 0; i < 2; i++) {
                uint32_t addr = abase + (arow + i * 16) * 128
                              + (((uint32_t)(half * 64 + kk * 32) + akh) ^ lxor);
                ldsm4(a[i], addr);
            }
#pragma unroll
            for (int i = 0; i < 2; i++)
#pragma unroll
                for (int j = 0; j < 8; j++)
                    mma16816(acc[i][j], a[i], &bb[kk][j * 2]);
        }
    }

    // ---- register-resident epilogue: +be, LN, GELU, +char (char from smem) ----
    {
        const float* bes = sp;                    // combined bias
        float* P = reinterpret_cast<float*>(smem + SM_PART);   // [64][4][2]
#pragma unroll
        for (int i = 0; i < 2; i++) {
            float sA = 0.f, qA = 0.f, sB = 0.f, qB = 0.f;
#pragma unroll
            for (int j = 0; j < 8; j++) {
                const int n = wn * 64 + j * 8 + (lid & 3) * 2;
                float f0 = acc[i][j][0] + bes[n];
                float f1 = acc[i][j][1] + bes[n + 1];
                float f2 = acc[i][j][2] + bes[n];
                float f3 = acc[i][j][3] + bes[n + 1];
                acc[i][j][0] = f0; acc[i][j][1] = f1;
                acc[i][j][2] = f2; acc[i][j][3] = f3;
                sA += f0 + f1; qA += f0 * f0 + f1 * f1;
                sB += f2 + f3; qB += f2 * f2 + f3 * f3;
            }
            sA += __shfl_xor_sync(0xffffffffu, sA, 1);
            qA += __shfl_xor_sync(0xffffffffu, qA, 1);
            sB += __shfl_xor_sync(0xffffffffu, sB, 1);
            qB += __shfl_xor_sync(0xffffffffu, qB, 1);
            sA += __shfl_xor_sync(0xffffffffu, sA, 2);
            qA += __shfl_xor_sync(0xffffffffu, qA, 2);
            sB += __shfl_xor_sync(0xffffffffu, sB, 2);
            qB += __shfl_xor_sync(0xffffffffu, qB, 2);
            if ((lid & 3) == 0) {
                const int rA = wm * 32 + i * 16 + (lid >> 2);
                const int rB = rA + 8;
                P[rA * 8 + wn * 2 + 0] = sA; P[rA * 8 + wn * 2 + 1] = qA;
                P[rB * 8 + wn * 2 + 0] = sB; P[rB * 8 + wn * 2 + 1] = qB;
            }
        }
        __syncthreads();

        const float* gms = sp + HD;
        const float* bts = sp + 2 * HD;
#pragma unroll
        for (int i = 0; i < 2; i++) {
            const int rA = wm * 32 + i * 16 + (lid >> 2);
            const int rB = rA + 8;
            float2 pa0 = *reinterpret_cast<const float2*>(P + rA * 8 + 0);
            float2 pa1 = *reinterpret_cast<const float2*>(P + rA * 8 + 2);
            float2 pa2 = *reinterpret_cast<const float2*>(P + rA * 8 + 4);
            float2 pa3 = *reinterpret_cast<const float2*>(P + rA * 8 + 6);
            float2 pb0 = *reinterpret_cast<const float2*>(P + rB * 8 + 0);
            float2 pb1 = *reinterpret_cast<const float2*>(P + rB * 8 + 2);
            float2 pb2 = *reinterpret_cast<const float2*>(P + rB * 8 + 4);
            float2 pb3 = *reinterpret_cast<const float2*>(P + rB * 8 + 6);
            float sA = pa0.x + pa1.x + pa2.x + pa3.x;
            float qA = pa0.y + pa1.y + pa2.y + pa3.y;
            float sB = pb0.x + pb1.x + pb2.x + pb3.x;
            float qB = pb0.y + pb1.y + pb2.y + pb3.y;
            const float muA = sA * (1.0f / HD);
            const float rsA = rsqrtf(qA * (1.0f / HD) - muA * muA + 1e-5f);
            const float muB = sB * (1.0f / HD);
            const float rsB = rsqrtf(qB * (1.0f / HD) - muB * muB + 1e-5f);
            const size_t gA = (r0 + rA) * HD, gB = (r0 + rB) * HD;
            const uint32_t rxA = ((uint32_t)(rA & 7)) << 4;   // rB&7 == rA&7
#pragma unroll
            for (int j = 0; j < 8; j++) {
                const int cl = j * 8 + (lid & 3) * 2;
                const int n = wn * 64 + cl;
                const float g0 = gms[n], g1 = gms[n + 1];
                const float t0 = bts[n], t1 = bts[n + 1];
                const uint32_t co = ((uint32_t)(cl * 2)) ^ rxA;
                __half2 hcA = *reinterpret_cast<const __half2*>(
                    smem + SM_CHAR + wn * 8192 + rA * 128 + co);
                __half2 hcB = *reinterpret_cast<const __half2*>(
                    smem + SM_CHAR + wn * 8192 + rB * 128 + co);
                float2 chA = __half22float2(hcA);
                float2 chB = __half22float2(hcB);
                float hA0 = (acc[i][j][0] - muA) * rsA * g0 + t0;
                float hA1 = (acc[i][j][1] - muA) * rsA * g1 + t1;
                float hB0 = (acc[i][j][2] - muB) * rsB * g0 + t0;
                float hB1 = (acc[i][j][3] - muB) * rsB * g1 + t1;
                float2 oA, oB;
                oA.x = chA.x + gelu_t(hA0);
                oA.y = chA.y + gelu_t(hA1);
                oB.x = chB.x + gelu_t(hB0);
                oB.y = chB.y + gelu_t(hB1);
                *reinterpret_cast<float2*>(outp + gA + n) = oA;
                *reinterpret_cast<float2*>(outp + gB + n) = oB;
            }
        }
    }
}

// ---------------- launch ----------------
extern "C" void kernel_launch(void* const* d_in, const int* in_sizes, int n_in,
                              void* d_out, int out_size) {
    const float* cemb  = (const float*)d_in[0];
    const int*   alig  = (const int*)d_in[1];
    const float* dec   = (const float*)d_in[2];
    const float* W1    = (const float*)d_in[3];
    const float* b1    = (const float*)d_in[4];
    const float* W2    = (const float*)d_in[5];
    const float* b2    = (const float*)d_in[6];
    const float* gamma = (const float*)d_in[7];
    const float* beta  = (const float*)d_in[8];
    float* outp = (float*)d_out;

    prep_comb<<<257, 256>>>(W1, b1, W2, b2);
    prep_wimg<<<64, 256>>>();

    cudaFuncSetAttribute(syl_main, cudaFuncAttributeMaxDynamicSharedMemorySize, SMEM_TOTAL);
    const int rows  = in_sizes[0] / HD;     // B * Lc = 131072 (from char elem count)
    const int tiles = rows / TILE_M;        // 2048
    syl_main<<<tiles, THREADS, SMEM_TOTAL>>>(cemb, alig, dec, gamma, beta, outp);
}